// round 1
// baseline (speedup 1.0000x reference)
#include <cuda_runtime.h>
#include <cuda_bf16.h>
#include <cstdint>
#include <math.h>

// ---------------------------------------------------------------------------
// UnfusedGemma4TextExperts: out = sum_e (gelu(X Gw_e^T) * (X Uw_e^T)) Dw_e^T / E
// E=8, T=8192, H=2048, F=1024. All fp32 in/out; compute in tf32 (RNA-rounded)
// via mma.sync.m16n8k8 tensor-core path. rel_err target ~3e-4.
// ---------------------------------------------------------------------------

#define BM 128
#define BN 128
#define BK 16

// Scratch (allocation-free per harness rules): per-expert intermediates.
__device__ __align__(128) float g_up [8192u * 1024u];
__device__ __align__(128) float g_act[8192u * 1024u];

__device__ __forceinline__ float tf32_rna(float x) {
    float y;
    asm("cvt.rna.tf32.f32 %0, %1;" : "=f"(y) : "f"(x));
    return y;
}

__device__ __forceinline__ float gelu_tanh(float x) {
    // jax.nn.gelu(approximate=True)
    float x3 = x * x * x;
    return 0.5f * x * (1.0f + tanhf(0.7978845608028654f * (x + 0.044715f * x3)));
}

// MODE 0: C_up(g_up)   = A @ B^T                      (A=X,      B=up_w[e])
// MODE 1: C_act(g_act) = gelu(A @ B^T) * g_up         (A=X,      B=gate_w[e])
// MODE 2: C            = (g_act @ B^T) * 1/8          (overwrite, expert 0)
// MODE 3: C           += (g_act @ B^T) * 1/8          (accumulate)
template <int MODE>
__global__ __launch_bounds__(256, 2)
void gemm_tf32_kernel(const float* __restrict__ Ain, const float* __restrict__ B,
                      float* __restrict__ C, int M, int N, int K)
{
    __shared__ float sA[2][BM * BK];
    __shared__ float sB[2][BN * BK];

    const float* __restrict__ A = (MODE >= 2) ? (const float*)g_act : Ain;

    const int tid   = threadIdx.x;
    const int lane  = tid & 31;
    const int warp  = tid >> 5;
    const int warpM = warp & 1;   // 2 warps along M
    const int warpN = warp >> 1;  // 4 warps along N
    const int m0 = blockIdx.y * BM;
    const int n0 = blockIdx.x * BN;

    // ---- global->shared copy plan (fragment-permuted smem layout) ----
    // A frag (m16k8): per-lane 4 regs stored contiguously -> LDS.128 at load.
    // B frag (k8n8):  per-lane 2 regs stored contiguously -> LDS.64 at load.
    const float* gA[2];
    const float* gB[2];
    int offA[2], offB[2];
#pragma unroll
    for (int it = 0; it < 2; ++it) {
        int li = tid + it * 256;     // 0..511
        int r  = li >> 2;            // row within tile (0..127)
        int kc = li & 3;             // which float4 along K (0..3)
        gA[it] = A + (size_t)(m0 + r) * K + kc * 4;
        gB[it] = B + (size_t)(n0 + r) * K + kc * 4;
        int ks = kc >> 1;            // k-step (0..1) within BK=16
        {   // A: tile tm (16 rows), lane = (rr&7)*4 + j, reg = (rr>=8) + 2*(k>=4)
            int tm  = r >> 4, rr = r & 15;
            int reg = ((rr >> 3) & 1) + (kc & 1) * 2;
            offA[it] = ((tm * 2 + ks) * 32 + (rr & 7) * 4) * 4 + reg;
        }
        {   // B: tile tn (8 rows=n), lane = nn*4 + j, reg = (k>=4)
            int tn  = r >> 3, nn = r & 7;
            int reg = kc & 1;
            offB[it] = ((tn * 2 + ks) * 32 + nn * 4) * 2 + reg;
        }
    }

    float acc[4][4][4];
#pragma unroll
    for (int i = 0; i < 4; ++i)
#pragma unroll
        for (int j = 0; j < 4; ++j)
#pragma unroll
            for (int v = 0; v < 4; ++v) acc[i][j][v] = 0.0f;

    float4 ra[2], rb[2];
    const int nk = K >> 4;

    // prologue: stage 0
#pragma unroll
    for (int it = 0; it < 2; ++it) {
        ra[it] = *reinterpret_cast<const float4*>(gA[it]);
        rb[it] = *reinterpret_cast<const float4*>(gB[it]);
    }
#pragma unroll
    for (int it = 0; it < 2; ++it) {
        sA[0][offA[it] + 0]  = tf32_rna(ra[it].x);
        sA[0][offA[it] + 4]  = tf32_rna(ra[it].y);
        sA[0][offA[it] + 8]  = tf32_rna(ra[it].z);
        sA[0][offA[it] + 12] = tf32_rna(ra[it].w);
        sB[0][offB[it] + 0]  = tf32_rna(rb[it].x);
        sB[0][offB[it] + 2]  = tf32_rna(rb[it].y);
        sB[0][offB[it] + 4]  = tf32_rna(rb[it].z);
        sB[0][offB[it] + 6]  = tf32_rna(rb[it].w);
    }
    __syncthreads();

    for (int kt = 0; kt < nk; ++kt) {
        const int cur = kt & 1;
        if (kt + 1 < nk) {
#pragma unroll
            for (int it = 0; it < 2; ++it) {
                ra[it] = *reinterpret_cast<const float4*>(gA[it] + (size_t)(kt + 1) * BK);
                rb[it] = *reinterpret_cast<const float4*>(gB[it] + (size_t)(kt + 1) * BK);
            }
        }
        // ---- compute BK=16 (two k8 steps) ----
#pragma unroll
        for (int ks = 0; ks < 2; ++ks) {
            uint32_t af[4][4];
            uint32_t bf[4][2];
#pragma unroll
            for (int i = 0; i < 4; ++i) {
                int tm = warpM * 4 + i;
                float4 v = *reinterpret_cast<const float4*>(
                    &sA[cur][((tm * 2 + ks) * 32 + lane) * 4]);
                af[i][0] = __float_as_uint(v.x); af[i][1] = __float_as_uint(v.y);
                af[i][2] = __float_as_uint(v.z); af[i][3] = __float_as_uint(v.w);
            }
#pragma unroll
            for (int j = 0; j < 4; ++j) {
                int tn = warpN * 4 + j;
                float2 v = *reinterpret_cast<const float2*>(
                    &sB[cur][((tn * 2 + ks) * 32 + lane) * 2]);
                bf[j][0] = __float_as_uint(v.x); bf[j][1] = __float_as_uint(v.y);
            }
#pragma unroll
            for (int i = 0; i < 4; ++i)
#pragma unroll
                for (int j = 0; j < 4; ++j) {
                    asm volatile(
                        "mma.sync.aligned.m16n8k8.row.col.f32.tf32.tf32.f32 "
                        "{%0,%1,%2,%3}, {%4,%5,%6,%7}, {%8,%9}, {%0,%1,%2,%3};\n"
                        : "+f"(acc[i][j][0]), "+f"(acc[i][j][1]),
                          "+f"(acc[i][j][2]), "+f"(acc[i][j][3])
                        : "r"(af[i][0]), "r"(af[i][1]), "r"(af[i][2]), "r"(af[i][3]),
                          "r"(bf[j][0]), "r"(bf[j][1]));
                }
        }
        if (kt + 1 < nk) {
            const int nxt = cur ^ 1;
#pragma unroll
            for (int it = 0; it < 2; ++it) {
                sA[nxt][offA[it] + 0]  = tf32_rna(ra[it].x);
                sA[nxt][offA[it] + 4]  = tf32_rna(ra[it].y);
                sA[nxt][offA[it] + 8]  = tf32_rna(ra[it].z);
                sA[nxt][offA[it] + 12] = tf32_rna(ra[it].w);
                sB[nxt][offB[it] + 0]  = tf32_rna(rb[it].x);
                sB[nxt][offB[it] + 2]  = tf32_rna(rb[it].y);
                sB[nxt][offB[it] + 4]  = tf32_rna(rb[it].z);
                sB[nxt][offB[it] + 6]  = tf32_rna(rb[it].w);
            }
            __syncthreads();
        }
    }

    // ---- epilogue ----
    const int r0 = lane >> 2;
    const int c0 = (lane & 3) * 2;
#pragma unroll
    for (int i = 0; i < 4; ++i) {
        int row = m0 + warpM * 64 + i * 16 + r0;
#pragma unroll
        for (int j = 0; j < 4; ++j) {
            int col = n0 + warpN * 32 + j * 8 + c0;
#pragma unroll
            for (int h = 0; h < 2; ++h) {
                int rr = row + h * 8;
                float v0 = acc[i][j][h * 2 + 0];
                float v1 = acc[i][j][h * 2 + 1];
                size_t idx = (size_t)rr * N + col;
                if (MODE == 0) {
                    *reinterpret_cast<float2*>(&g_up[idx]) = make_float2(v0, v1);
                } else if (MODE == 1) {
                    float2 u = *reinterpret_cast<const float2*>(&g_up[idx]);
                    *reinterpret_cast<float2*>(&g_act[idx]) =
                        make_float2(gelu_tanh(v0) * u.x, gelu_tanh(v1) * u.y);
                } else if (MODE == 2) {
                    *reinterpret_cast<float2*>(&C[idx]) =
                        make_float2(v0 * 0.125f, v1 * 0.125f);
                } else {
                    float2 o = *reinterpret_cast<const float2*>(&C[idx]);
                    *reinterpret_cast<float2*>(&C[idx]) =
                        make_float2(o.x + v0 * 0.125f, o.y + v1 * 0.125f);
                }
            }
        }
    }
}

extern "C" void kernel_launch(void* const* d_in, const int* in_sizes, int n_in,
                              void* d_out, int out_size)
{
    // metadata order: hidden_states, routing_weights, selected_experts,
    //                 gate_w, up_w, down_w  (routing inputs unused: uniform 1/E)
    const float* X  = (const float*)d_in[0];
    const float* gw = (const float*)d_in[3];
    const float* uw = (const float*)d_in[4];
    const float* dw = (const float*)d_in[5];
    float* out = (float*)d_out;

    const int T = 8192, H = 2048, F = 1024, E = 8;

    dim3 blk(256, 1, 1);
    dim3 gridA(F / BN, T / BM, 1);  // 8 x 64   (up / gate GEMMs, N=F, K=H)
    dim3 gridD(H / BN, T / BM, 1);  // 16 x 64  (down GEMM,       N=H, K=F)

    for (int e = 0; e < E; ++e) {
        const float* gwe = gw + (size_t)e * F * H;
        const float* uwe = uw + (size_t)e * F * H;
        const float* dwe = dw + (size_t)e * H * F;

        gemm_tf32_kernel<0><<<gridA, blk>>>(X, uwe, nullptr, T, F, H);
        gemm_tf32_kernel<1><<<gridA, blk>>>(X, gwe, nullptr, T, F, H);
        if (e == 0)
            gemm_tf32_kernel<2><<<gridD, blk>>>(nullptr, dwe, out, T, H, F);
        else
            gemm_tf32_kernel<3><<<gridD, blk>>>(nullptr, dwe, out, T, H, F);
    }
}

// round 5
// speedup vs baseline: 5.6808x; 5.6808x over previous
#include <cuda.h>
#include <cuda_runtime.h>
#include <cuda_fp16.h>
#include <cstdint>
#include <math.h>

// ---------------------------------------------------------------------------
// UnfusedGemma4TextExperts, sm_103 (no 'a' features available from this
// toolchain): fp16 mma.sync.m16n8k16 + ldmatrix + TMA/mbarrier pipeline.
// out = sum_e (gelu(X Gw_e^T) * (X Uw_e^T)) Dw_e^T / 8
// E=8, T=8192, H=2048, F=1024. fp32 I/O, fp16 operands, fp32 accumulate.
// ---------------------------------------------------------------------------

// ------------------------- scratch (allocation-free) -----------------------
__device__ __align__(1024) __half g_Xh [8192u * 2048u];        // 32 MB
__device__ __align__(1024) __half g_uwh[8u * 1024u * 2048u];   // 32 MB
__device__ __align__(1024) __half g_gwh[8u * 1024u * 2048u];   // 32 MB
__device__ __align__(1024) __half g_dwh[8u * 2048u * 1024u];   // 32 MB
__device__ __align__(1024) __half g_act[8u * 8192u * 1024u];   // 128 MB

// ------------------------------ PTX helpers --------------------------------
__device__ __forceinline__ uint32_t smem_to_u32(const void* p) {
    uint32_t a;
    asm("{ .reg .u64 t; cvta.to.shared.u64 t, %1; cvt.u32.u64 %0, t; }"
        : "=r"(a) : "l"(p));
    return a;
}

__device__ __forceinline__ uint32_t elect_one_pred() {
    uint32_t pred;
    asm volatile(
        "{\n\t.reg .pred p;\n\t"
        "elect.sync _|p, 0xFFFFFFFF;\n\t"
        "selp.b32 %0, 1, 0, p;\n\t}"
        : "=r"(pred));
    return pred;
}

#define MBARRIER_INIT(addr, cnt) \
    asm volatile("mbarrier.init.shared.b64 [%0], %1;" \
                 :: "r"((uint32_t)(addr)), "r"((uint32_t)(cnt)) : "memory")

#define MBARRIER_EXPECT_TX(addr, bytes) \
    asm volatile("mbarrier.arrive.expect_tx.shared.b64 _, [%0], %1;" \
                 :: "r"((uint32_t)(addr)), "r"((uint32_t)(bytes)) : "memory")

#define MBARRIER_ARRIVE(addr) \
    asm volatile("mbarrier.arrive.shared.b64 _, [%0];" \
                 :: "r"((uint32_t)(addr)) : "memory")

#define MBARRIER_WAIT_PARITY(addr, parity) do {                              \
    uint32_t _mbar = (uint32_t)(addr);                                       \
    uint32_t _par  = (uint32_t)(parity);                                     \
    uint32_t _done;                                                          \
    asm volatile(                                                            \
        "{\n\t.reg .pred p;\n\t"                                             \
        "mbarrier.try_wait.parity.acquire.cta.shared::cta.b64 p, [%1], %2;\n\t" \
        "selp.b32 %0, 1, 0, p;\n\t}"                                         \
        : "=r"(_done) : "r"(_mbar), "r"(_par) : "memory");                   \
    if (!_done) {                                                            \
        asm volatile(                                                        \
            "{\n\t.reg .pred P1;\n\t"                                        \
            "WAIT_LOOP_%=:\n\t"                                              \
            "mbarrier.try_wait.parity.acquire.cta.shared::cta.b64 P1, [%0], %1, 0x989680;\n\t" \
            "@P1 bra.uni WAIT_DONE_%=;\n\t"                                  \
            "bra.uni WAIT_LOOP_%=;\n\t"                                      \
            "WAIT_DONE_%=:\n\t}"                                             \
            :: "r"(_mbar), "r"(_par) : "memory");                            \
    }                                                                        \
} while (0)

#define TMA_LOAD_3D(smem_addr, tensor_map, cx, cy, cz, mbar) \
    asm volatile( \
        "cp.async.bulk.tensor.3d.shared::cta.global.tile.mbarrier::complete_tx::bytes " \
        "[%0], [%1, {%2, %3, %4}], [%5];" \
        :: "r"((uint32_t)(smem_addr)), "l"(tensor_map), \
           "r"((int32_t)(cx)), "r"((int32_t)(cy)), "r"((int32_t)(cz)), \
           "r"((uint32_t)(mbar)) : "memory")

#define FENCE_PROXY_ASYNC_SHARED_CTA() \
    asm volatile("fence.proxy.async.shared::cta;" ::: "memory")

__device__ __forceinline__ void ldsm_x4(uint32_t r[4], uint32_t addr) {
    asm volatile("ldmatrix.sync.aligned.m8n8.x4.shared.b16 {%0,%1,%2,%3}, [%4];"
                 : "=r"(r[0]), "=r"(r[1]), "=r"(r[2]), "=r"(r[3]) : "r"(addr));
}

__device__ __forceinline__ void mma_f16(float c[4], const uint32_t a[4],
                                        uint32_t b0, uint32_t b1) {
    asm volatile(
        "mma.sync.aligned.m16n8k16.row.col.f32.f16.f16.f32 "
        "{%0,%1,%2,%3},{%4,%5,%6,%7},{%8,%9},{%0,%1,%2,%3};"
        : "+f"(c[0]), "+f"(c[1]), "+f"(c[2]), "+f"(c[3])
        : "r"(a[0]), "r"(a[1]), "r"(a[2]), "r"(a[3]), "r"(b0), "r"(b1));
}

__device__ __forceinline__ float gelu_tanh(float x) {
    float x3 = x * x * x;
    return 0.5f * x * (1.0f + tanhf(0.7978845608028654f * (x + 0.044715f * x3)));
}

// SW128 swizzled address within a TMA-loaded tile (128B rows):
// byte = row*128 + ((chunk ^ (row&7)) << 4), chunk = 16B unit along K.
__device__ __forceinline__ uint32_t sw_addr(uint32_t tile, int row, int chunk) {
    return tile + row * 128 + (((chunk ^ (row & 7)) & 7) << 4);
}

#define ST 6
#define STAGE_UG 32768   // A 16KB + Bu 8KB + Bg 8KB
#define STAGE_DN 32768   // A 16KB + B 16KB
#define SMEM_SZ (1024 + 1024 + ST * 32768)

// ------------------------------- prepass -----------------------------------
__global__ void f32_to_f16(const float4* __restrict__ in, uint2* __restrict__ out,
                           int n4) {
    int i = blockIdx.x * blockDim.x + threadIdx.x;
    int stride = gridDim.x * blockDim.x;
    for (; i < n4; i += stride) {
        float4 v = in[i];
        __half2 h0 = __floats2half2_rn(v.x, v.y);
        __half2 h1 = __floats2half2_rn(v.z, v.w);
        uint2 u;
        u.x = *reinterpret_cast<uint32_t*>(&h0);
        u.y = *reinterpret_cast<uint32_t*>(&h1);
        out[i] = u;
    }
}

// --------------------- kernel 1: fused up+gate+gelu -------------------------
// grid (F/64=16, T/128=64, E=8). CTA: 128m x 64n of BOTH up and gate GEMMs,
// act = fp16(gelu(gate)*up) -> g_act[e].  K=2048, BK=64 halves, 6-stage TMA.
__global__ __launch_bounds__(288, 1)
void k_upgate(const __grid_constant__ CUtensorMap mX,
              const __grid_constant__ CUtensorMap mU,
              const __grid_constant__ CUtensorMap mG)
{
    extern __shared__ char smem[];
    const uint32_t base  = (smem_to_u32(smem) + 1023) & ~1023u;
    const uint32_t tile0 = base + 1024;
    const int tid = threadIdx.x, wid = tid >> 5, lane = tid & 31;

    const uint32_t mb_full  = base;        // ST x 8B
    const uint32_t mb_empty = base + 128;  // ST x 8B

    if (tid == 0) {
        for (int s = 0; s < ST; ++s) {
            MBARRIER_INIT(mb_full  + s * 8, 1);
            MBARRIER_INIT(mb_empty + s * 8, 8);
        }
        FENCE_PROXY_ASYNC_SHARED_CTA();
    }
    __syncthreads();

    const int m0 = blockIdx.y * 128;
    const int n0 = blockIdx.x * 64;
    const int e  = blockIdx.z;
    const int NK = 32;                      // 2048 / 64

    if (wid == 8) {                         // ---- TMA producer ----
        if (elect_one_pred()) {
            int s = 0, ph = 1;
            for (int kt = 0; kt < NK; ++kt) {
                MBARRIER_WAIT_PARITY(mb_empty + s * 8, ph);
                MBARRIER_EXPECT_TX(mb_full + s * 8, STAGE_UG);
                uint32_t st = tile0 + s * STAGE_UG;
                TMA_LOAD_3D(st,         &mX, kt * 64, m0, 0, mb_full + s * 8);
                TMA_LOAD_3D(st + 16384, &mU, kt * 64, n0, e, mb_full + s * 8);
                TMA_LOAD_3D(st + 24576, &mG, kt * 64, n0, e, mb_full + s * 8);
                if (++s == ST) { s = 0; ph ^= 1; }
            }
        }
        return;
    }

    // ---- compute warps (8): warp tile 32m x 32n per GEMM ----
    const int wm = wid & 3;                 // 4 warps along m (32 each)
    const int wn = wid >> 2;                // 2 warps along n (32 each)

    float au[2][4][4], ag[2][4][4];
#pragma unroll
    for (int i = 0; i < 2; ++i)
#pragma unroll
        for (int j = 0; j < 4; ++j)
#pragma unroll
            for (int v = 0; v < 4; ++v) { au[i][j][v] = 0.f; ag[i][j][v] = 0.f; }

    const int rowA0 = wm * 32 + (lane & 15);        // + t*16
    const int cbA   = lane >> 4;
    const int rowB0 = wn * 32 + ((lane >> 4) & 1) * 8 + (lane & 7);  // + t2*16
    const int cbB   = (lane >> 3) & 1;

    int s = 0, ph = 0;
    for (int kt = 0; kt < NK; ++kt) {
        MBARRIER_WAIT_PARITY(mb_full + s * 8, ph);
        const uint32_t stA = tile0 + s * STAGE_UG;
        const uint32_t stU = stA + 16384;
        const uint32_t stG = stA + 24576;
#pragma unroll
        for (int step = 0; step < 4; ++step) {
            uint32_t a[2][4];
#pragma unroll
            for (int t = 0; t < 2; ++t)
                ldsm_x4(a[t], sw_addr(stA, rowA0 + t * 16, step * 2 + cbA));
            uint32_t bu[2][4], bg[2][4];
#pragma unroll
            for (int t2 = 0; t2 < 2; ++t2) {
                ldsm_x4(bu[t2], sw_addr(stU, rowB0 + t2 * 16, step * 2 + cbB));
                ldsm_x4(bg[t2], sw_addr(stG, rowB0 + t2 * 16, step * 2 + cbB));
            }
#pragma unroll
            for (int i = 0; i < 2; ++i)
#pragma unroll
                for (int j = 0; j < 4; ++j) {
                    mma_f16(au[i][j], a[i], bu[j >> 1][(j & 1) * 2], bu[j >> 1][(j & 1) * 2 + 1]);
                    mma_f16(ag[i][j], a[i], bg[j >> 1][(j & 1) * 2], bg[j >> 1][(j & 1) * 2 + 1]);
                }
        }
        if (elect_one_pred()) MBARRIER_ARRIVE(mb_empty + s * 8);
        if (++s == ST) { s = 0; ph ^= 1; }
    }

    // ---- epilogue: act = fp16(gelu(gate) * up) ----
    __half* actp = g_act + (size_t)e * 8192u * 1024u;
#pragma unroll
    for (int i = 0; i < 2; ++i) {
        int r = m0 + wm * 32 + i * 16 + (lane >> 2);
#pragma unroll
        for (int j = 0; j < 4; ++j) {
            int c = n0 + wn * 32 + j * 8 + (lane & 3) * 2;
            __half2 h0 = __floats2half2_rn(gelu_tanh(ag[i][j][0]) * au[i][j][0],
                                           gelu_tanh(ag[i][j][1]) * au[i][j][1]);
            __half2 h1 = __floats2half2_rn(gelu_tanh(ag[i][j][2]) * au[i][j][2],
                                           gelu_tanh(ag[i][j][3]) * au[i][j][3]);
            *reinterpret_cast<__half2*>(actp + (size_t)r * 1024 + c)       = h0;
            *reinterpret_cast<__half2*>(actp + (size_t)(r + 8) * 1024 + c) = h1;
        }
    }
}

// ------------------- kernel 2: down-proj over all experts ------------------
// grid (H/128=16, T/128=64). CTA: 128m x 128n, K = 8 experts x 1024 = 8192,
// accumulate fp32 in registers, out = D * 0.125.
__global__ __launch_bounds__(288, 1)
void k_down(const __grid_constant__ CUtensorMap mA,
            const __grid_constant__ CUtensorMap mD,
            float* __restrict__ out)
{
    extern __shared__ char smem[];
    const uint32_t base  = (smem_to_u32(smem) + 1023) & ~1023u;
    const uint32_t tile0 = base + 1024;
    const int tid = threadIdx.x, wid = tid >> 5, lane = tid & 31;

    const uint32_t mb_full  = base;
    const uint32_t mb_empty = base + 128;

    if (tid == 0) {
        for (int s = 0; s < ST; ++s) {
            MBARRIER_INIT(mb_full  + s * 8, 1);
            MBARRIER_INIT(mb_empty + s * 8, 8);
        }
        FENCE_PROXY_ASYNC_SHARED_CTA();
    }
    __syncthreads();

    const int m0 = blockIdx.y * 128;
    const int n0 = blockIdx.x * 128;
    const int NI = 128;                     // 8 experts x (1024/64)

    if (wid == 8) {                         // ---- TMA producer ----
        if (elect_one_pred()) {
            int s = 0, ph = 1;
            for (int i = 0; i < NI; ++i) {
                int e = i >> 4, kt = i & 15;
                MBARRIER_WAIT_PARITY(mb_empty + s * 8, ph);
                MBARRIER_EXPECT_TX(mb_full + s * 8, STAGE_DN);
                uint32_t st = tile0 + s * STAGE_DN;
                TMA_LOAD_3D(st,         &mA, kt * 64, m0, e, mb_full + s * 8);
                TMA_LOAD_3D(st + 16384, &mD, kt * 64, n0, e, mb_full + s * 8);
                if (++s == ST) { s = 0; ph ^= 1; }
            }
        }
        return;
    }

    // ---- compute warps: warp tile 32m x 64n ----
    const int wm = wid & 3;
    const int wn = wid >> 2;

    float ac[2][8][4];
#pragma unroll
    for (int i = 0; i < 2; ++i)
#pragma unroll
        for (int j = 0; j < 8; ++j)
#pragma unroll
            for (int v = 0; v < 4; ++v) ac[i][j][v] = 0.f;

    const int rowA0 = wm * 32 + (lane & 15);
    const int cbA   = lane >> 4;
    const int rowB0 = wn * 64 + ((lane >> 4) & 1) * 8 + (lane & 7);
    const int cbB   = (lane >> 3) & 1;

    int s = 0, ph = 0;
    for (int it = 0; it < NI; ++it) {
        MBARRIER_WAIT_PARITY(mb_full + s * 8, ph);
        const uint32_t stA = tile0 + s * STAGE_DN;
        const uint32_t stB = stA + 16384;
#pragma unroll
        for (int step = 0; step < 4; ++step) {
            uint32_t a[2][4];
#pragma unroll
            for (int t = 0; t < 2; ++t)
                ldsm_x4(a[t], sw_addr(stA, rowA0 + t * 16, step * 2 + cbA));
            uint32_t b[4][4];
#pragma unroll
            for (int t2 = 0; t2 < 4; ++t2)
                ldsm_x4(b[t2], sw_addr(stB, rowB0 + t2 * 16, step * 2 + cbB));
#pragma unroll
            for (int i = 0; i < 2; ++i)
#pragma unroll
                for (int j = 0; j < 8; ++j)
                    mma_f16(ac[i][j], a[i], b[j >> 1][(j & 1) * 2], b[j >> 1][(j & 1) * 2 + 1]);
        }
        if (elect_one_pred()) MBARRIER_ARRIVE(mb_empty + s * 8);
        if (++s == ST) { s = 0; ph ^= 1; }
    }

    // ---- epilogue: out = acc/8 ----
#pragma unroll
    for (int i = 0; i < 2; ++i) {
        int r = m0 + wm * 32 + i * 16 + (lane >> 2);
#pragma unroll
        for (int j = 0; j < 8; ++j) {
            int c = n0 + wn * 64 + j * 8 + (lane & 3) * 2;
            *reinterpret_cast<float2*>(out + (size_t)r * 2048 + c) =
                make_float2(ac[i][j][0] * 0.125f, ac[i][j][1] * 0.125f);
            *reinterpret_cast<float2*>(out + (size_t)(r + 8) * 2048 + c) =
                make_float2(ac[i][j][2] * 0.125f, ac[i][j][3] * 0.125f);
        }
    }
}

// --------------------------------- host ------------------------------------
typedef CUresult (*PFN_tmapEncode)(
    CUtensorMap*, CUtensorMapDataType, cuuint32_t, void*,
    const cuuint64_t*, const cuuint64_t*, const cuuint32_t*, const cuuint32_t*,
    CUtensorMapInterleave, CUtensorMapSwizzle, CUtensorMapL2promotion,
    CUtensorMapFloatOOBfill);

static PFN_tmapEncode get_tmap_fn() {
    static PFN_tmapEncode fn = nullptr;
    if (!fn) {
        void* p = nullptr;
        cudaDriverEntryPointQueryResult qr;
        cudaGetDriverEntryPoint("cuTensorMapEncodeTiled", &p, cudaEnableDefault, &qr);
        fn = (PFN_tmapEncode)p;
    }
    return fn;
}

static void make_map_f16(CUtensorMap* m, void* ptr, uint64_t d0, uint64_t d1,
                         uint64_t d2, uint32_t b0, uint32_t b1) {
    cuuint64_t dims[3]    = {d0, d1, d2};
    cuuint64_t strides[2] = {d0 * 2, d0 * d1 * 2};
    cuuint32_t box[3]     = {b0, b1, 1};
    cuuint32_t es[3]      = {1, 1, 1};
    get_tmap_fn()(m, CU_TENSOR_MAP_DATA_TYPE_FLOAT16, 3, ptr, dims, strides,
                  box, es, CU_TENSOR_MAP_INTERLEAVE_NONE,
                  CU_TENSOR_MAP_SWIZZLE_128B, CU_TENSOR_MAP_L2_PROMOTION_L2_128B,
                  CU_TENSOR_MAP_FLOAT_OOB_FILL_NONE);
}

extern "C" void kernel_launch(void* const* d_in, const int* in_sizes, int n_in,
                              void* d_out, int out_size)
{
    const float* X  = (const float*)d_in[0];
    const float* gw = (const float*)d_in[3];
    const float* uw = (const float*)d_in[4];
    const float* dw = (const float*)d_in[5];
    float* out = (float*)d_out;

    __half *pX, *pU, *pG, *pD, *pA;
    cudaGetSymbolAddress((void**)&pX, g_Xh);
    cudaGetSymbolAddress((void**)&pU, g_uwh);
    cudaGetSymbolAddress((void**)&pG, g_gwh);
    cudaGetSymbolAddress((void**)&pD, g_dwh);
    cudaGetSymbolAddress((void**)&pA, g_act);

    const int n4 = 4194304;  // 16.78M floats / 4
    f32_to_f16<<<2048, 256>>>((const float4*)X,  (uint2*)pX, n4);
    f32_to_f16<<<2048, 256>>>((const float4*)uw, (uint2*)pU, n4);
    f32_to_f16<<<2048, 256>>>((const float4*)gw, (uint2*)pG, n4);
    f32_to_f16<<<2048, 256>>>((const float4*)dw, (uint2*)pD, n4);

    CUtensorMap mX, mU, mG, mA, mD;
    make_map_f16(&mX, pX, 2048, 8192, 1, 64, 128);   // X    [T,H]
    make_map_f16(&mU, pU, 2048, 1024, 8, 64, 64);    // up_w [E,F,H]
    make_map_f16(&mG, pG, 2048, 1024, 8, 64, 64);    // gate_w
    make_map_f16(&mA, pA, 1024, 8192, 8, 64, 128);   // act  [E,T,F]
    make_map_f16(&mD, pD, 1024, 2048, 8, 64, 128);   // down_w [E,H,F]

    cudaFuncSetAttribute(k_upgate, cudaFuncAttributeMaxDynamicSharedMemorySize, SMEM_SZ);
    cudaFuncSetAttribute(k_down,   cudaFuncAttributeMaxDynamicSharedMemorySize, SMEM_SZ);

    k_upgate<<<dim3(16, 64, 8), 288, SMEM_SZ>>>(mX, mU, mG);
    k_down  <<<dim3(16, 64, 1), 288, SMEM_SZ>>>(mA, mD, out);
}